// round 15
// baseline (speedup 1.0000x reference)
#include <cuda_runtime.h>
#include <cuda_fp16.h>
#include <cstdint>
#include <cstddef>

#define DI __device__ __forceinline__

// ---------------- problem constants ----------------
constexpr int BATCH = 131072;
constexpr int HD    = 128;        // H == IN == 128
constexpr int KTOT  = 256;        // x(128) ++ h_prev(128)
constexpr int BM    = 128;        // batch rows per CTA
constexpr int BN    = 128;        // gate-columns per CTA (32 j's x 4 gates, interleaved)
constexpr int KC    = 64;         // fp16 K per stage
constexpr int NKCH  = KTOT / KC;  // 4
constexpr int NTHR  = 256;        // 8 warps: 4(m) x 2(n), warp tile 32x64
constexpr int NSTG  = 3;          // triple buffer -> ONE barrier per stage

// smem layout (bytes): per stage: A[128 rows][72 f16] + B[128 rows][72 f16]
constexpr int ROWB    = 144;                     // 64 f16 = 128B data + 16B pad (LDSM conflict-free)
constexpr int A_BYTES = BM * ROWB;               // 18432
constexpr int B_BYTES = BN * ROWB;               // 18432
constexpr int STG_B   = A_BYTES + B_BYTES;       // 36864
constexpr int ZPITCH  = 136;                     // fp32 epilogue tile pitch (floats)
constexpr int SM_BYTES = NSTG * STG_B;           // 110592 (z-tile 69632 overlays); 2 CTAs/SM

// fp16 pre-converted weights only (activations converted in-kernel now)
static __device__ __half g_Bt[512 * KTOT];       // n-major [n=512][k=256], n = 4*j+gate

// ---------------- PTX helpers ----------------
DI uint32_t smem_u32(const void* p) {
    uint32_t a;
    asm("{ .reg .u64 t; cvta.to.shared.u64 t, %1; cvt.u32.u64 %0, t; }" : "=r"(a) : "l"(p));
    return a;
}
DI void cp_async16(uint32_t dst, const void* src) {
    asm volatile("cp.async.cg.shared.global [%0], [%1], 16;" :: "r"(dst), "l"(src));
}
DI void cp_commit() { asm volatile("cp.async.commit_group;" ::: "memory"); }
template<int N> DI void cp_wait() { asm volatile("cp.async.wait_group %0;" :: "n"(N) : "memory"); }

DI void ldsm4(uint32_t* r, uint32_t addr) {
    asm volatile("ldmatrix.sync.aligned.m8n8.x4.shared.b16 {%0,%1,%2,%3}, [%4];"
        : "=r"(r[0]), "=r"(r[1]), "=r"(r[2]), "=r"(r[3]) : "r"(addr));
}
DI void mma16(float* d, const uint32_t* a, const uint32_t* b) {
    asm volatile("mma.sync.aligned.m16n8k16.row.col.f32.f16.f16.f32 "
        "{%0,%1,%2,%3}, {%4,%5,%6,%7}, {%8,%9}, {%0,%1,%2,%3};"
        : "+f"(d[0]), "+f"(d[1]), "+f"(d[2]), "+f"(d[3])
        : "r"(a[0]), "r"(a[1]), "r"(a[2]), "r"(a[3]), "r"(b[0]), "r"(b[1]));
}
DI float mufu_tanh(float z) {
    float r;
    asm("tanh.approx.f32 %0, %1;" : "=f"(r) : "f"(z));
    return r;
}
DI float fast_sigmoid(float z) { return fmaf(mufu_tanh(0.5f * z), 0.5f, 0.5f); }

// ---------------- prologue: weights -> fp16, n-major, gate-interleaved ----------------
__global__ void prep_w_kernel(
    const float* __restrict__ Wi, const float* __restrict__ Ui,
    const float* __restrict__ Wf, const float* __restrict__ Uf,
    const float* __restrict__ Wg, const float* __restrict__ Ug,
    const float* __restrict__ Wo, const float* __restrict__ Uo)
{
    int idx = blockIdx.x * blockDim.x + threadIdx.x;  // 0 .. 131071
    int k    = idx & 255;
    int n    = idx >> 8;          // n = 4*j + gate
    int j    = n >> 2;
    int gate = n & 3;
    const float* W = (gate == 0) ? Wi : (gate == 1) ? Wf : (gate == 2) ? Wg : Wo;
    const float* U = (gate == 0) ? Ui : (gate == 1) ? Uf : (gate == 2) ? Ug : Uo;
    float v = (k < HD) ? W[k * HD + j] : U[(k - HD) * HD + j];
    g_Bt[n * KTOT + k] = __float2half_rn(v);
}

// ---------------- B stage loader (cp.async, 1 commit group) ----------------
DI void load_B_stage(uint32_t sbase, int buf, int s, int n0w, int tid)
{
    uint32_t bbuf = sbase + buf * STG_B + A_BYTES;
    #pragma unroll
    for (int i = 0; i < 4; i++) {
        int t = tid + i * NTHR;
        int r = t >> 3, c = t & 7;
        cp_async16(bbuf + r * ROWB + c * 16,
                   g_Bt + (size_t)(n0w + r) * KTOT + s * KC + c * 8);
    }
    cp_commit();
}

// ---------------- in-kernel A conversion (fp32 -> fp16) ----------------
// chunk c covers rows [c*32, c*32+32); thread handles 8 contiguous fp32 (two float4)
DI void ldg_chunk(float4* st, const float* __restrict__ asrc, int m0, int kc, int c, int tid)
{
    const int r = c * 32 + (tid >> 3);
    const float* p = asrc + (size_t)(m0 + r) * HD + kc + (tid & 7) * 8;
    st[0] = *reinterpret_cast<const float4*>(p);
    st[1] = *reinterpret_cast<const float4*>(p + 4);
}
DI void sts_chunk(uint32_t abuf, const float4* st, int c, int tid)
{
    __half2 h0 = __floats2half2_rn(st[0].x, st[0].y);
    __half2 h1 = __floats2half2_rn(st[0].z, st[0].w);
    __half2 h2 = __floats2half2_rn(st[1].x, st[1].y);
    __half2 h3 = __floats2half2_rn(st[1].z, st[1].w);
    uint32_t u0 = *reinterpret_cast<uint32_t*>(&h0);
    uint32_t u1 = *reinterpret_cast<uint32_t*>(&h1);
    uint32_t u2 = *reinterpret_cast<uint32_t*>(&h2);
    uint32_t u3 = *reinterpret_cast<uint32_t*>(&h3);
    uint32_t dst = abuf + (uint32_t)((c * 32 + (tid >> 3)) * ROWB + (tid & 7) * 16);
    asm volatile("st.shared.v4.b32 [%0], {%1,%2,%3,%4};"
                 :: "r"(dst), "r"(u0), "r"(u1), "r"(u2), "r"(u3) : "memory");
}
// synchronous full-stage convert (prologue only; reg-light serialized chunks)
DI void convert_A_full(uint32_t abuf, const float* __restrict__ asrc, int m0, int kc, int tid)
{
    #pragma unroll 1
    for (int c = 0; c < 4; c++) {
        float4 st[2];
        ldg_chunk(st, asrc, m0, kc, c, tid);
        sts_chunk(abuf, st, c, tid);
    }
}

// ---------------- main fused kernel ----------------
__global__ void __launch_bounds__(NTHR, 2) lstm_kernel(
    const float* __restrict__ x,  const float* __restrict__ hp,
    const float* __restrict__ cprev,
    const float* __restrict__ bi, const float* __restrict__ bf,
    const float* __restrict__ bg, const float* __restrict__ bo,
    float* __restrict__ out)
{
    extern __shared__ float sm[];
    const uint32_t sbase = smem_u32(sm);
    const int tid  = threadIdx.x;
    const int lane = tid & 31;
    const int wid  = tid >> 5;
    const int wm   = wid & 3;        // warp m-index (4)
    const int wn   = wid >> 2;       // warp n-index (2), warp tile 32x64
    const int q    = lane & 3;
    const int g    = lane >> 2;

    const int mblk = blockIdx.x >> 2;
    const int nblk = blockIdx.x & 3;
    const int m0   = mblk * BM;
    const int n0w  = nblk * BN;      // weight-row base (interleaved n)
    const int j0   = nblk * 32;      // hidden-unit base

    // per-lane ldmatrix address offsets
    const uint32_t aoff = ((lane & 7) + ((lane >> 3) & 1) * 8) * ROWB + ((lane >> 4) & 1) * 16;
    const uint32_t boff = ((lane & 7) + ((lane >> 4) & 1) * 8) * ROWB + ((lane >> 3) & 1) * 16;

    // ---- init accumulators with biases (n = 4*j + gate interleave) ----
    float acc[2][8][4];
    #pragma unroll
    for (int nt = 0; nt < 8; nt++) {
        const int ne = n0w + wn * 64 + nt * 8 + 2 * q;
        const int no = ne + 1;
        const int ge = ne & 3, je = ne >> 2;
        const int go_ = no & 3, jo = no >> 2;
        const float* bpe = (ge == 0) ? bi : (ge == 1) ? bf : (ge == 2) ? bg : bo;
        const float* bpo = (go_ == 0) ? bi : (go_ == 1) ? bf : (go_ == 2) ? bg : bo;
        const float be = __ldg(bpe + je);
        const float bo_v = __ldg(bpo + jo);
        #pragma unroll
        for (int mt = 0; mt < 2; mt++) {
            acc[mt][nt][0] = be;  acc[mt][nt][1] = bo_v;
            acc[mt][nt][2] = be;  acc[mt][nt][3] = bo_v;
        }
    }

    // ---- prologue: stages 0,1 (A in-kernel convert; B cp.async) ----
    convert_A_full(sbase + 0 * STG_B, x, m0, 0,  tid);   // stage 0: x, k 0..63
    convert_A_full(sbase + 1 * STG_B, x, m0, KC, tid);   // stage 1: x, k 64..127
    load_B_stage(sbase, 0, 0, n0w, tid);
    load_B_stage(sbase, 1, 1, n0w, tid);

    // ---- triple-buffered GEMM over 4 K-stages, one barrier per stage ----
    float4 stg[2][2];   // A-conversion staging, double-buffered chunk
    #pragma unroll
    for (int s = 0; s < NKCH; s++) {
        const int buf = s % NSTG;
        if (s < NKCH - 1) cp_wait<1>(); else cp_wait<0>();
        __syncthreads();

        const bool conv = (s + 2 < NKCH);       // stages 2,3 source = hp
        const int  buf2 = (s + 2) % NSTG;
        const int  kc2  = ((s + 2) & 1) * KC;
        const uint32_t abuf2 = sbase + buf2 * STG_B;
        if (conv) {
            load_B_stage(sbase, buf2, s + 2, n0w, tid);
            ldg_chunk(stg[0], hp, m0, kc2, 0, tid);   // prefetch chunk 0
        }

        const uint32_t abase = sbase + buf * STG_B + (wm * 32) * ROWB + aoff;
        const uint32_t bbase = sbase + buf * STG_B + A_BYTES + (wn * 64) * ROWB + boff;

        #pragma unroll
        for (int ks = 0; ks < 4; ks++) {
            uint32_t afr[2][4], bfr[4][4];
            ldsm4(afr[0], abase + ks * 32);
            ldsm4(afr[1], abase + 16 * ROWB + ks * 32);
            #pragma unroll
            for (int i = 0; i < 4; i++)
                ldsm4(bfr[i], bbase + i * 16 * ROWB + ks * 32);
            #pragma unroll
            for (int mt = 0; mt < 2; mt++)
                #pragma unroll
                for (int nt = 0; nt < 8; nt++)
                    mma16(acc[mt][nt], afr[mt], &bfr[nt >> 1][(nt & 1) * 2]);

            if (conv) {
                if (ks < 3) ldg_chunk(stg[(ks + 1) & 1], hp, m0, kc2, ks + 1, tid);
                sts_chunk(abuf2, stg[ks & 1], ks, tid);   // cvt+store chunk loaded last iter
            }
        }
    }

    // ---- spill accumulators to smem z-tile [row][n], pitch ZPITCH ----
    __syncthreads();   // all warps done with stage buffers (z overlays them)
    #pragma unroll
    for (int mt = 0; mt < 2; mt++) {
        const int r0 = wm * 32 + mt * 16 + g;
        #pragma unroll
        for (int nt = 0; nt < 8; nt++) {
            const int n0 = wn * 64 + nt * 8 + 2 * q;
            *reinterpret_cast<float2*>(&sm[r0 * ZPITCH + n0]) =
                make_float2(acc[mt][nt][0], acc[mt][nt][1]);
            *reinterpret_cast<float2*>(&sm[(r0 + 8) * ZPITCH + n0]) =
                make_float2(acc[mt][nt][2], acc[mt][nt][3]);
        }
    }
    __syncthreads();

    // ---- fused LSTM epilogue: 128 rows x 32 j's (biases already in z) ----
    const int jl = tid & 31;
    const int rw = tid >> 5;         // 0..7
    const int jg = j0 + jl;
    float* hout = out;
    float* cout = out + (size_t)BATCH * HD;

    #pragma unroll 4
    for (int it = 0; it < 16; it++) {
        const int row = it * 8 + rw;
        float4 z = *reinterpret_cast<const float4*>(&sm[row * ZPITCH + 4 * jl]);
        const float ig = fast_sigmoid(z.x);
        const float fg = fast_sigmoid(z.y);
        const float cc = mufu_tanh(z.z);
        const float og = fast_sigmoid(z.w);
        const size_t go = (size_t)(m0 + row) * HD + jg;
        const float c0 = __ldg(cprev + go);
        const float cn = fg * c0 + ig * cc;
        const float hn = og * mufu_tanh(cn);
        hout[go] = hn;
        cout[go] = cn;
    }
}

// ---------------- launch ----------------
extern "C" void kernel_launch(void* const* d_in, const int* in_sizes, int n_in,
                              void* d_out, int out_size)
{
    const float* x  = (const float*)d_in[0];
    const float* hp = (const float*)d_in[1];
    const float* cp = (const float*)d_in[2];
    const float* Wi = (const float*)d_in[3];
    const float* Ui = (const float*)d_in[4];
    const float* bi = (const float*)d_in[5];
    const float* Wf = (const float*)d_in[6];
    const float* Uf = (const float*)d_in[7];
    const float* bf = (const float*)d_in[8];
    const float* Wg = (const float*)d_in[9];
    const float* Ug = (const float*)d_in[10];
    const float* bg = (const float*)d_in[11];
    const float* Wo = (const float*)d_in[12];
    const float* Uo = (const float*)d_in[13];
    const float* bo = (const float*)d_in[14];
    float* out = (float*)d_out;

    cudaFuncSetAttribute(lstm_kernel, cudaFuncAttributeMaxDynamicSharedMemorySize, SM_BYTES);

    prep_w_kernel<<<128, 1024>>>(Wi, Ui, Wf, Uf, Wg, Ug, Wo, Uo);
    lstm_kernel<<<(BATCH / BM) * 4, NTHR, SM_BYTES>>>(x, hp, cp, bi, bf, bg, bo, out);
}

// round 16
// speedup vs baseline: 1.2465x; 1.2465x over previous
#include <cuda_runtime.h>
#include <cuda_fp16.h>
#include <cstdint>
#include <cstddef>

#define DI __device__ __forceinline__

// ---------------- problem constants ----------------
constexpr int BATCH = 131072;
constexpr int HD    = 128;        // H == IN == 128
constexpr int KTOT  = 256;        // x(128) ++ h_prev(128)
constexpr int BM    = 128;        // batch rows per CTA
constexpr int BN    = 128;        // gate-columns per CTA (32 j's x 4 gates, interleaved)
constexpr int KC    = 64;         // fp16 K per stage
constexpr int NKCH  = KTOT / KC;  // 4
constexpr int NTHR  = 256;        // 8 warps: 4(m) x 2(n), warp tile 32x64
constexpr int NSTG  = 3;          // triple buffer -> ONE barrier per stage

constexpr size_t ACT_HALF = (size_t)BATCH * HD;   // elements in x (== h_prev)

// smem layout (bytes): per stage: A[128 rows][72 f16] + B[128 rows][72 f16]
constexpr int ROWB    = 144;                     // 64 f16 = 128B data + 16B pad (LDSM conflict-free)
constexpr int A_BYTES = BM * ROWB;               // 18432
constexpr int B_BYTES = BN * ROWB;               // 18432
constexpr int STG_B   = A_BYTES + B_BYTES;       // 36864
constexpr int ZPITCH  = 136;                     // fp32 epilogue tile pitch (floats)
constexpr int SM_BYTES = NSTG * STG_B;           // 110592 (z-tile 69632 overlays); 2 CTAs/SM

// fp16 pre-converted operands
static __device__ __half g_Bt[512 * KTOT];       // weights n-major [n=512][k=256], n = 4*j+gate
static __device__ __half g_acts[2 * ACT_HALF];   // [x ; h_prev] fp16

// prep grid split: acts handled 8 floats/thread, weights 1 elem/thread
constexpr int ACT_BLOCKS = (int)(2 * ACT_HALF / 8 / 1024);   // 4096
constexpr int W_BLOCKS   = 512 * KTOT / 1024;                // 128

// ---------------- PTX helpers ----------------
DI uint32_t smem_u32(const void* p) {
    uint32_t a;
    asm("{ .reg .u64 t; cvta.to.shared.u64 t, %1; cvt.u32.u64 %0, t; }" : "=r"(a) : "l"(p));
    return a;
}
DI void cp_async16(uint32_t dst, const void* src) {
    asm volatile("cp.async.cg.shared.global [%0], [%1], 16;" :: "r"(dst), "l"(src));
}
DI void cp_commit() { asm volatile("cp.async.commit_group;" ::: "memory"); }
template<int N> DI void cp_wait() { asm volatile("cp.async.wait_group %0;" :: "n"(N) : "memory"); }

DI void ldsm4(uint32_t* r, uint32_t addr) {
    asm volatile("ldmatrix.sync.aligned.m8n8.x4.shared.b16 {%0,%1,%2,%3}, [%4];"
        : "=r"(r[0]), "=r"(r[1]), "=r"(r[2]), "=r"(r[3]) : "r"(addr));
}
DI void mma16(float* d, const uint32_t* a, const uint32_t* b) {
    asm volatile("mma.sync.aligned.m16n8k16.row.col.f32.f16.f16.f32 "
        "{%0,%1,%2,%3}, {%4,%5,%6,%7}, {%8,%9}, {%0,%1,%2,%3};"
        : "+f"(d[0]), "+f"(d[1]), "+f"(d[2]), "+f"(d[3])
        : "r"(a[0]), "r"(a[1]), "r"(a[2]), "r"(a[3]), "r"(b[0]), "r"(b[1]));
}
DI float mufu_tanh(float z) {
    float r;
    asm("tanh.approx.f32 %0, %1;" : "=f"(r) : "f"(z));
    return r;
}
DI float fast_sigmoid(float z) { return fmaf(mufu_tanh(0.5f * z), 0.5f, 0.5f); }

// ---------------- fused prologue: weights + activations -> fp16 ----------------
__global__ void prep_all_kernel(
    const float* __restrict__ x,  const float* __restrict__ hp,
    const float* __restrict__ Wi, const float* __restrict__ Ui,
    const float* __restrict__ Wf, const float* __restrict__ Uf,
    const float* __restrict__ Wg, const float* __restrict__ Ug,
    const float* __restrict__ Wo, const float* __restrict__ Uo)
{
    int b = blockIdx.x;
    if (b < ACT_BLOCKS) {
        size_t e = ((size_t)b * 1024 + threadIdx.x) * 8;  // float index, 8 per thread
        const float* src = (e < ACT_HALF) ? (x + e) : (hp + (e - ACT_HALF));
        float4 v0 = *reinterpret_cast<const float4*>(src);
        float4 v1 = *reinterpret_cast<const float4*>(src + 4);
        __half2 h0 = __floats2half2_rn(v0.x, v0.y);
        __half2 h1 = __floats2half2_rn(v0.z, v0.w);
        __half2 h2 = __floats2half2_rn(v1.x, v1.y);
        __half2 h3 = __floats2half2_rn(v1.z, v1.w);
        uint4 pk;
        pk.x = *reinterpret_cast<uint32_t*>(&h0);
        pk.y = *reinterpret_cast<uint32_t*>(&h1);
        pk.z = *reinterpret_cast<uint32_t*>(&h2);
        pk.w = *reinterpret_cast<uint32_t*>(&h3);
        *reinterpret_cast<uint4*>(g_acts + e) = pk;   // one 16B store
    } else {
        int idx = (b - ACT_BLOCKS) * 1024 + threadIdx.x;  // 0 .. 131071
        int k    = idx & 255;
        int n    = idx >> 8;          // n = 4*j + gate
        int j    = n >> 2;
        int gate = n & 3;
        const float* W = (gate == 0) ? Wi : (gate == 1) ? Wf : (gate == 2) ? Wg : Wo;
        const float* U = (gate == 0) ? Ui : (gate == 1) ? Uf : (gate == 2) ? Ug : Uo;
        float v = (k < HD) ? W[k * HD + j] : U[(k - HD) * HD + j];
        g_Bt[n * KTOT + k] = __float2half_rn(v);
    }
}

// ---------------- stage loader (fp16 smem, 1 commit group) ----------------
DI void load_stage(uint32_t sbase, int buf, int s, int m0, int n0w, int tid)
{
    uint32_t abuf = sbase + buf * STG_B;
    uint32_t bbuf = abuf + A_BYTES;
    const __half* asrc = g_acts + ((s < 2) ? 0 : ACT_HALF);
    const int kc = (s & 1) * KC;
    // A: 128 rows x 64 f16 (128B) -> 1024 cp16 -> 4 per thread
    #pragma unroll
    for (int i = 0; i < 4; i++) {
        int t = tid + i * NTHR;
        int r = t >> 3, c = t & 7;
        cp_async16(abuf + r * ROWB + c * 16,
                   asrc + (size_t)(m0 + r) * HD + kc + c * 8);
    }
    // B: 128 n-rows x 64 f16 -> 1024 cp16 -> 4 per thread
    #pragma unroll
    for (int i = 0; i < 4; i++) {
        int t = tid + i * NTHR;
        int r = t >> 3, c = t & 7;
        cp_async16(bbuf + r * ROWB + c * 16,
                   g_Bt + (size_t)(n0w + r) * KTOT + s * KC + c * 8);
    }
    cp_commit();
}

// ---------------- main fused kernel ----------------
__global__ void __launch_bounds__(NTHR, 2) lstm_kernel(
    const float* __restrict__ cprev,
    const float* __restrict__ bi, const float* __restrict__ bf,
    const float* __restrict__ bg, const float* __restrict__ bo,
    float* __restrict__ out)
{
    extern __shared__ float sm[];
    const uint32_t sbase = smem_u32(sm);
    const int tid  = threadIdx.x;
    const int lane = tid & 31;
    const int wid  = tid >> 5;
    const int wm   = wid & 3;        // warp m-index (4)
    const int wn   = wid >> 2;       // warp n-index (2), warp tile 32x64
    const int q    = lane & 3;
    const int g    = lane >> 2;

    const int mblk = blockIdx.x >> 2;
    const int nblk = blockIdx.x & 3;
    const int m0   = mblk * BM;
    const int n0w  = nblk * BN;      // weight-row base (interleaved n)
    const int j0   = nblk * 32;      // hidden-unit base

    // per-lane ldmatrix address offsets (within a 16x32B-row tile at a row base)
    const uint32_t aoff = ((lane & 7) + ((lane >> 3) & 1) * 8) * ROWB + ((lane >> 4) & 1) * 16;
    const uint32_t boff = ((lane & 7) + ((lane >> 4) & 1) * 8) * ROWB + ((lane >> 3) & 1) * 16;

    // ---- init accumulators with biases (n = 4*j + gate interleave) ----
    float acc[2][8][4];
    #pragma unroll
    for (int nt = 0; nt < 8; nt++) {
        const int ne = n0w + wn * 64 + nt * 8 + 2 * q;      // even n of this thread
        const int no = ne + 1;
        const int ge = ne & 3, je = ne >> 2;
        const int go_ = no & 3, jo = no >> 2;
        const float* bpe = (ge == 0) ? bi : (ge == 1) ? bf : (ge == 2) ? bg : bo;
        const float* bpo = (go_ == 0) ? bi : (go_ == 1) ? bf : (go_ == 2) ? bg : bo;
        const float be = __ldg(bpe + je);
        const float bo_v = __ldg(bpo + jo);
        #pragma unroll
        for (int mt = 0; mt < 2; mt++) {
            acc[mt][nt][0] = be;  acc[mt][nt][1] = bo_v;
            acc[mt][nt][2] = be;  acc[mt][nt][3] = bo_v;
        }
    }

    // ---- triple-buffered GEMM over 4 K-stages, one barrier per stage ----
    load_stage(sbase, 0, 0, m0, n0w, tid);
    load_stage(sbase, 1, 1, m0, n0w, tid);

    #pragma unroll
    for (int s = 0; s < NKCH; s++) {
        const int buf = s % NSTG;
        if (s < NKCH - 1) cp_wait<1>(); else cp_wait<0>();
        __syncthreads();
        if (s + 2 < NKCH) load_stage(sbase, (s + 2) % NSTG, s + 2, m0, n0w, tid);

        const uint32_t abase = sbase + buf * STG_B + (wm * 32) * ROWB + aoff;
        const uint32_t bbase = sbase + buf * STG_B + A_BYTES + (wn * 64) * ROWB + boff;

        #pragma unroll
        for (int ks = 0; ks < 4; ks++) {
            uint32_t afr[2][4], bfr[4][4];
            ldsm4(afr[0], abase + ks * 32);
            ldsm4(afr[1], abase + 16 * ROWB + ks * 32);
            #pragma unroll
            for (int i = 0; i < 4; i++)
                ldsm4(bfr[i], bbase + i * 16 * ROWB + ks * 32);
            #pragma unroll
            for (int mt = 0; mt < 2; mt++)
                #pragma unroll
                for (int nt = 0; nt < 8; nt++)
                    mma16(acc[mt][nt], afr[mt], &bfr[nt >> 1][(nt & 1) * 2]);
        }
    }

    // ---- spill accumulators to smem z-tile [row][n], pitch ZPITCH ----
    __syncthreads();   // all warps done with stage buffers (z overlays them)
    #pragma unroll
    for (int mt = 0; mt < 2; mt++) {
        const int r0 = wm * 32 + mt * 16 + g;
        #pragma unroll
        for (int nt = 0; nt < 8; nt++) {
            const int n0 = wn * 64 + nt * 8 + 2 * q;
            *reinterpret_cast<float2*>(&sm[r0 * ZPITCH + n0]) =
                make_float2(acc[mt][nt][0], acc[mt][nt][1]);
            *reinterpret_cast<float2*>(&sm[(r0 + 8) * ZPITCH + n0]) =
                make_float2(acc[mt][nt][2], acc[mt][nt][3]);
        }
    }
    __syncthreads();

    // ---- fused LSTM epilogue: 128 rows x 32 j's (biases already in z) ----
    const int jl = tid & 31;
    const int rw = tid >> 5;         // 0..7
    const int jg = j0 + jl;
    float* hout = out;
    float* cout = out + (size_t)BATCH * HD;

    #pragma unroll 4
    for (int it = 0; it < 16; it++) {
        const int row = it * 8 + rw;
        float4 z = *reinterpret_cast<const float4*>(&sm[row * ZPITCH + 4 * jl]);
        const float ig = fast_sigmoid(z.x);
        const float fg = fast_sigmoid(z.y);
        const float cc = mufu_tanh(z.z);
        const float og = fast_sigmoid(z.w);
        const size_t go = (size_t)(m0 + row) * HD + jg;
        const float c0 = __ldg(cprev + go);
        const float cn = fg * c0 + ig * cc;
        const float hn = og * mufu_tanh(cn);
        hout[go] = hn;
        cout[go] = cn;
    }
}

// ---------------- launch ----------------
extern "C" void kernel_launch(void* const* d_in, const int* in_sizes, int n_in,
                              void* d_out, int out_size)
{
    const float* x  = (const float*)d_in[0];
    const float* hp = (const float*)d_in[1];
    const float* cp = (const float*)d_in[2];
    const float* Wi = (const float*)d_in[3];
    const float* Ui = (const float*)d_in[4];
    const float* bi = (const float*)d_in[5];
    const float* Wf = (const float*)d_in[6];
    const float* Uf = (const float*)d_in[7];
    const float* bf = (const float*)d_in[8];
    const float* Wg = (const float*)d_in[9];
    const float* Ug = (const float*)d_in[10];
    const float* bg = (const float*)d_in[11];
    const float* Wo = (const float*)d_in[12];
    const float* Uo = (const float*)d_in[13];
    const float* bo = (const float*)d_in[14];
    float* out = (float*)d_out;

    cudaFuncSetAttribute(lstm_kernel, cudaFuncAttributeMaxDynamicSharedMemorySize, SM_BYTES);

    prep_all_kernel<<<ACT_BLOCKS + W_BLOCKS, 1024>>>(x, hp, Wi, Ui, Wf, Uf, Wg, Ug, Wo, Uo);
    lstm_kernel<<<(BATCH / BM) * 4, NTHR, SM_BYTES>>>(cp, bi, bf, bg, bo, out);
}